// round 1
// baseline (speedup 1.0000x reference)
#include <cuda_runtime.h>
#include <math.h>

// log(entmax_bisect_1.5(X)) row-wise. X: (rows, 32000) fp32, out same shape.
//
// Math: p(z) = relu(z)^2 with z = 0.5*X - tau, tau chosen so sum(p) = 1.
// Dense support (guaranteed by the input distribution) gives tau in closed
// form from S1 = sum(0.5*X), S2 = sum((0.5*X)^2):
//     d*tau^2 - 2*S1*tau + (S2 - 1) = 0  =>  tau = (S1 - sqrt(S1^2 - d(S2-1)))/d
// Fallback: if tau > min (support not dense), run the exact reference
// 50-iteration bisection over the SMEM-resident row.

constexpr int D  = 32000;
constexpr int D4 = D / 4;
constexpr int NT = 1024;
constexpr int NW = NT / 32;

__device__ __forceinline__ float wsum(float v) {
#pragma unroll
    for (int o = 16; o; o >>= 1) v += __shfl_xor_sync(0xffffffffu, v, o);
    return v;
}
__device__ __forceinline__ float wmin(float v) {
#pragma unroll
    for (int o = 16; o; o >>= 1) v = fminf(v, __shfl_xor_sync(0xffffffffu, v, o));
    return v;
}
__device__ __forceinline__ float wmax(float v) {
#pragma unroll
    for (int o = 16; o; o >>= 1) v = fmaxf(v, __shfl_xor_sync(0xffffffffu, v, o));
    return v;
}

// Block-wide sum of relu(sx[i] - tau)^2, broadcast to all threads.
// Used only on the (never-expected) sparse-support fallback path.
__device__ float block_relu2_sum(const float* sx, float tau, float* redbuf, float* bc) {
    float acc = 0.f;
    for (int i = threadIdx.x; i < D; i += NT) {
        float t = fmaxf(sx[i] - tau, 0.f);
        acc = fmaf(t, t, acc);
    }
    acc = wsum(acc);
    int wid = threadIdx.x >> 5, lid = threadIdx.x & 31;
    __syncthreads();                    // protect redbuf/bc reuse across calls
    if (lid == 0) redbuf[wid] = acc;
    __syncthreads();
    if (threadIdx.x == 0) {
        float s = 0.f;
#pragma unroll
        for (int w = 0; w < NW; ++w) s += redbuf[w];
        *bc = s;
    }
    __syncthreads();
    return *bc;
}

__global__ void __launch_bounds__(NT, 1)
log_entmax_kernel(const float* __restrict__ X, float* __restrict__ Y) {
    extern __shared__ float sx[];                  // 32000 floats = 125 KB
    __shared__ float redA[NW], redB[NW], redC[NW], redD[NW];
    __shared__ float s_tau, s_logsum, s_flag, s_mx, s_bc;

    const int tid = threadIdx.x;
    const int wid = tid >> 5, lid = tid & 31;
    const float4* __restrict__ x4 = reinterpret_cast<const float4*>(X) + (size_t)blockIdx.x * D4;
    float4* __restrict__ y4       = reinterpret_cast<float4*>(Y)       + (size_t)blockIdx.x * D4;
    float4* s4 = reinterpret_cast<float4*>(sx);

    // ---- Pass 1: load (scaled by alpha-1 = 0.5) into SMEM + stats ----
    float s1 = 0.f, s2 = 0.f, mn = INFINITY, mx = -INFINITY;
    for (int i = tid; i < D4; i += NT) {
        float4 v = x4[i];
        v.x *= 0.5f; v.y *= 0.5f; v.z *= 0.5f; v.w *= 0.5f;
        s4[i] = v;
        s1 += (v.x + v.y) + (v.z + v.w);
        s2 = fmaf(v.x, v.x, s2); s2 = fmaf(v.y, v.y, s2);
        s2 = fmaf(v.z, v.z, s2); s2 = fmaf(v.w, v.w, s2);
        mn = fminf(mn, fminf(fminf(v.x, v.y), fminf(v.z, v.w)));
        mx = fmaxf(mx, fmaxf(fmaxf(v.x, v.y), fmaxf(v.z, v.w)));
    }
    s1 = wsum(s1); s2 = wsum(s2); mn = wmin(mn); mx = wmax(mx);
    if (lid == 0) { redA[wid] = s1; redB[wid] = s2; redC[wid] = mn; redD[wid] = mx; }
    __syncthreads();

    if (tid == 0) {
        float S1 = 0.f, S2 = 0.f, MN = INFINITY, MX = -INFINITY;
#pragma unroll
        for (int w = 0; w < NW; ++w) {
            S1 += redA[w]; S2 += redB[w];
            MN = fminf(MN, redC[w]); MX = fmaxf(MX, redD[w]);
        }
        const float k = (float)D;
        float disc  = fmaxf(fmaf(S1, S1, -k * (S2 - 1.0f)), 0.f);
        float tau   = (S1 - sqrtf(disc)) / k;
        float sum_p = fmaf(k * tau, tau, fmaf(-2.f * S1, tau, S2));
        s_tau = tau;
        s_mx  = MX;
        if (tau <= MN && sum_p > 0.f) {            // dense support: closed form valid
            s_logsum = __logf(sum_p);
            s_flag = 1.f;
        } else {
            s_flag = 0.f;
        }
    }
    __syncthreads();

    // ---- Fallback: exact reference bisection (block-uniform branch) ----
    if (s_flag == 0.f) {
        float mxv    = s_mx;
        float tau_lo = mxv - 1.0f;
        float tau_hi = mxv - sqrtf(1.0f / (float)D);
        float f_lo   = block_relu2_sum(sx, tau_lo, redA, &s_bc) - 1.0f;
        float dm     = tau_hi - tau_lo;
        float tau_m  = tau_lo;
        for (int it = 0; it < 50; ++it) {
            dm *= 0.5f;
            tau_m = tau_lo + dm;
            float f_m = block_relu2_sum(sx, tau_m, redA, &s_bc) - 1.0f;
            if (f_m * f_lo >= 0.f) tau_lo = tau_m;   // uniform across block
        }
        float sp = block_relu2_sum(sx, tau_m, redA, &s_bc);
        if (tid == 0) {
            s_tau = tau_m;
            s_logsum = __logf(sp);
        }
        __syncthreads();
    }

    const float tau    = s_tau;
    const float logsum = s_logsum;

    // ---- Pass 2: output log p = 2*log(x*0.5 - tau) - log(sum_p) ----
    for (int i = tid; i < D4; i += NT) {
        float4 v = s4[i];
        float4 r;
        float t;
        t = v.x - tau; r.x = (t > 0.f) ? fmaf(2.f, __logf(t), -logsum) : -INFINITY;
        t = v.y - tau; r.y = (t > 0.f) ? fmaf(2.f, __logf(t), -logsum) : -INFINITY;
        t = v.z - tau; r.z = (t > 0.f) ? fmaf(2.f, __logf(t), -logsum) : -INFINITY;
        t = v.w - tau; r.w = (t > 0.f) ? fmaf(2.f, __logf(t), -logsum) : -INFINITY;
        y4[i] = r;
    }
}

extern "C" void kernel_launch(void* const* d_in, const int* in_sizes, int n_in,
                              void* d_out, int out_size) {
    const float* X = (const float*)d_in[0];
    float* Y = (float*)d_out;
    const int rows = in_sizes[0] / D;
    cudaFuncSetAttribute(log_entmax_kernel,
                         cudaFuncAttributeMaxDynamicSharedMemorySize, D * (int)sizeof(float));
    log_entmax_kernel<<<rows, NT, D * sizeof(float)>>>(X, Y);
}

// round 2
// speedup vs baseline: 1.2862x; 1.2862x over previous
#include <cuda_runtime.h>
#include <math.h>

// log(entmax_bisect_1.5(X)) row-wise. X: (rows, 32000) fp32, out same shape.
//
// p(z) = relu(z)^2 with z = 0.5*X - tau, tau s.t. sum p = 1. Dense support
// (guaranteed by input distribution) gives closed-form tau from S1, S2:
//   d*tau^2 - 2*S1*tau + (S2 - 1) = 0  =>  tau = (S1 - sqrt(S1^2 - d(S2-1)))/d
// validated by tau <= min(z). Fallback: exact 50-iter reference bisection
// re-reading the row from global (L2-resident).
//
// No SMEM row buffer: pass 2 re-reads X, which is still L2-resident
// (3 CTAs/SM x 148 SMs x 128KB = 55MB << 126MB L2). Y stores use __stcs.

constexpr int D  = 32000;
constexpr int D4 = D / 4;
constexpr int NT = 512;
constexpr int NW = NT / 32;

__device__ __forceinline__ float wsum(float v) {
#pragma unroll
    for (int o = 16; o; o >>= 1) v += __shfl_xor_sync(0xffffffffu, v, o);
    return v;
}
__device__ __forceinline__ float wmin(float v) {
#pragma unroll
    for (int o = 16; o; o >>= 1) v = fminf(v, __shfl_xor_sync(0xffffffffu, v, o));
    return v;
}
__device__ __forceinline__ float wmax(float v) {
#pragma unroll
    for (int o = 16; o; o >>= 1) v = fmaxf(v, __shfl_xor_sync(0xffffffffu, v, o));
    return v;
}

// Block-wide sum of relu(0.5*x[i] - tau)^2 over the row, broadcast.
// Fallback path only (support not dense) — row is L2-resident.
__device__ float block_relu2_sum(const float4* __restrict__ x4, float tau,
                                 float* redbuf, float* bc) {
    float acc = 0.f;
    for (int i = threadIdx.x; i < D4; i += NT) {
        float4 v = x4[i];
        float t;
        t = fmaxf(fmaf(0.5f, v.x, -tau), 0.f); acc = fmaf(t, t, acc);
        t = fmaxf(fmaf(0.5f, v.y, -tau), 0.f); acc = fmaf(t, t, acc);
        t = fmaxf(fmaf(0.5f, v.z, -tau), 0.f); acc = fmaf(t, t, acc);
        t = fmaxf(fmaf(0.5f, v.w, -tau), 0.f); acc = fmaf(t, t, acc);
    }
    acc = wsum(acc);
    int wid = threadIdx.x >> 5, lid = threadIdx.x & 31;
    __syncthreads();
    if (lid == 0) redbuf[wid] = acc;
    __syncthreads();
    if (threadIdx.x == 0) {
        float s = 0.f;
#pragma unroll
        for (int w = 0; w < NW; ++w) s += redbuf[w];
        *bc = s;
    }
    __syncthreads();
    return *bc;
}

__global__ void __launch_bounds__(NT, 3)
log_entmax_kernel(const float* __restrict__ X, float* __restrict__ Y) {
    __shared__ float redA[NW], redB[NW], redC[NW], redD[NW];
    __shared__ float s_tau, s_logsum, s_flag, s_mx, s_bc;

    const int tid = threadIdx.x;
    const int wid = tid >> 5, lid = tid & 31;
    const float4* __restrict__ x4 = reinterpret_cast<const float4*>(X) + (size_t)blockIdx.x * D4;
    float4* __restrict__ y4       = reinterpret_cast<float4*>(Y)       + (size_t)blockIdx.x * D4;

    // ---- Pass 1: stream row from DRAM (fills L2), accumulate stats ----
    float s1 = 0.f, s2 = 0.f, mn = INFINITY, mx = -INFINITY;
    for (int i = tid; i < D4; i += NT) {
        float4 v = x4[i];
        v.x *= 0.5f; v.y *= 0.5f; v.z *= 0.5f; v.w *= 0.5f;
        s1 += (v.x + v.y) + (v.z + v.w);
        s2 = fmaf(v.x, v.x, s2); s2 = fmaf(v.y, v.y, s2);
        s2 = fmaf(v.z, v.z, s2); s2 = fmaf(v.w, v.w, s2);
        mn = fminf(mn, fminf(fminf(v.x, v.y), fminf(v.z, v.w)));
        mx = fmaxf(mx, fmaxf(fmaxf(v.x, v.y), fmaxf(v.z, v.w)));
    }
    s1 = wsum(s1); s2 = wsum(s2); mn = wmin(mn); mx = wmax(mx);
    if (lid == 0) { redA[wid] = s1; redB[wid] = s2; redC[wid] = mn; redD[wid] = mx; }
    __syncthreads();

    if (tid == 0) {
        float S1 = 0.f, S2 = 0.f, MN = INFINITY, MX = -INFINITY;
#pragma unroll
        for (int w = 0; w < NW; ++w) {
            S1 += redA[w]; S2 += redB[w];
            MN = fminf(MN, redC[w]); MX = fmaxf(MX, redD[w]);
        }
        const float k = (float)D;
        float disc  = fmaxf(fmaf(S1, S1, -k * (S2 - 1.0f)), 0.f);
        float tau   = (S1 - sqrtf(disc)) / k;
        float sum_p = fmaf(k * tau, tau, fmaf(-2.f * S1, tau, S2));
        s_tau = tau;
        s_mx  = MX;
        if (tau <= MN && sum_p > 0.f) {           // dense support: closed form valid
            s_logsum = __logf(sum_p);
            s_flag = 1.f;
        } else {
            s_flag = 0.f;
        }
    }
    __syncthreads();

    // ---- Fallback: exact reference bisection (block-uniform branch) ----
    if (s_flag == 0.f) {
        float mxv    = s_mx;
        float tau_lo = mxv - 1.0f;
        float tau_hi = mxv - sqrtf(1.0f / (float)D);
        float f_lo   = block_relu2_sum(x4, tau_lo, redA, &s_bc) - 1.0f;
        float dm     = tau_hi - tau_lo;
        float tau_m  = tau_lo;
        for (int it = 0; it < 50; ++it) {
            dm *= 0.5f;
            tau_m = tau_lo + dm;
            float f_m = block_relu2_sum(x4, tau_m, redA, &s_bc) - 1.0f;
            if (f_m * f_lo >= 0.f) tau_lo = tau_m;  // uniform across block
        }
        float sp = block_relu2_sum(x4, tau_m, redA, &s_bc);
        if (tid == 0) {
            s_tau = tau_m;
            s_logsum = __logf(sp);
        }
        __syncthreads();
    }

    const float tau    = s_tau;
    const float logsum = s_logsum;

    // ---- Pass 2: re-read X (L2 hit), write log p with streaming stores ----
    for (int i = tid; i < D4; i += NT) {
        float4 v = __ldcs(&x4[i]);   // evict-first: row is dead after this read
        float4 r;
        float t;
        t = fmaf(0.5f, v.x, -tau); r.x = (t > 0.f) ? fmaf(2.f, __logf(t), -logsum) : -INFINITY;
        t = fmaf(0.5f, v.y, -tau); r.y = (t > 0.f) ? fmaf(2.f, __logf(t), -logsum) : -INFINITY;
        t = fmaf(0.5f, v.z, -tau); r.z = (t > 0.f) ? fmaf(2.f, __logf(t), -logsum) : -INFINITY;
        t = fmaf(0.5f, v.w, -tau); r.w = (t > 0.f) ? fmaf(2.f, __logf(t), -logsum) : -INFINITY;
        __stcs(&y4[i], r);           // streaming store: don't pollute L2
    }
}

extern "C" void kernel_launch(void* const* d_in, const int* in_sizes, int n_in,
                              void* d_out, int out_size) {
    const float* X = (const float*)d_in[0];
    float* Y = (float*)d_out;
    const int rows = in_sizes[0] / D;
    log_entmax_kernel<<<rows, NT>>>(X, Y);
}